// round 14
// baseline (speedup 1.0000x reference)
#include <cuda_runtime.h>
#include <math.h>

// ---------------------------------------------------------------------------
// OneDimEquivalent scan, time-chunked (8 chunks x 512 steps, 160 warm-up).
//   v' = 0.8 v + 0.2 u ; k' = 0.8 k + g(k^2+u^2)*(0.28 k + 0.52 v') ; z = 2.1 k'
// g indexed in y = rsqrt(1+s), 128-cell LUT of line coeffs, lane-replicated
// 32x (zero-conflict LDS.64); x clamped -> index provably in [0,127].
// Staging traffic de-burst at QUAD granularity: flush (prev group), LDG
// prefetch (g+2) and STS stage (g+1) are folded into the compute loop, one
// slice per 4 steps, so the dependent table-LDS queues behind at most ~6
// wavefronts instead of 32+. 256 blocks, 2/SM, warp-private (syncwarp only).
// ---------------------------------------------------------------------------

#define B_DIM 4096
#define T_DIM 4096
#define CHUNKS 8
#define LCH 512
#define WARM 160              // rho^160 ~ 4e-5 truncation
#define TBL_N 128
#define CM 142.4f
#define CA (-15.38f)
#define MAGIC 12582912.0f
#define CAM (CA + MAGIC)
#define X_CAP 85.0f
#define UP_CAP 65.0f
#define INV_SQRT_2PI 0.3989422804014327f
#define NQ 96
#define BSTR 36               // overlay row stride in floats (144 B, 16B-aligned)

__device__ float  g_qw[NQ + 1];
__device__ float  g_val[TBL_N];
__device__ float2 g_tab[TBL_N];

// ---------------------------------------------------------------------------
__global__ void qw_kernel() {
    int j = threadIdx.x;
    if (j > NQ) return;
    const float h = 5.0f / (float)NQ;
    float z = h * (float)j;
    float w = (j == 0 || j == NQ) ? 0.5f * h : h;
    g_qw[j] = 2.0f * INV_SQRT_2PI * w * __expf(-0.5f * z * z);
}

__global__ void table_val_kernel() {
    int i = threadIdx.x;
    if (i >= TBL_N) return;
    float y = ((float)i - CA) / CM;
    float s = 1.0f / (y * y) - 1.0f;
    if (s < 0.0f) s = 0.0f;
    float d = sqrtf(s);
    const float h = 5.0f / (float)NQ;
    float dz = d * h;
    float x = 0.0f;
    float acc = 0.0f;
    #pragma unroll 4
    for (int j = 0; j <= NQ; ++j) {
        float e = __expf(-2.0f * x);
        float inv = __fdividef(1.0f, 1.0f + e);
        acc = fmaf(g_qw[j], 4.0f * e * inv * inv, acc);
        x += dz;
    }
    g_val[i] = acc;
}

__global__ void table_coef_kernel() {
    int i = threadIdx.x;
    if (i >= TBL_N) return;
    float a;
    if (i == 0)              a = g_val[1] - g_val[0];
    else if (i == TBL_N - 1) a = g_val[TBL_N - 1] - g_val[TBL_N - 2];
    else                     a = 0.5f * (g_val[i + 1] - g_val[i - 1]);
    g_tab[i].x = a;
    g_tab[i].y = g_val[i] - a * (float)i;
}

// ---------------------------------------------------------------------------
// Scan: grid (32 rowblocks, 8 chunks) x 128 threads. 2 blocks/SM.
// Shared: replicated table (32KB) + 2 overlay bufs 128*BSTR floats (36KB).
// ---------------------------------------------------------------------------
__global__ __launch_bounds__(128, 2)
void scan_kernel(const float* __restrict__ u, float* __restrict__ out) {
    extern __shared__ float smem[];
    float2* s_tab = (float2*)smem;
    float*  bufA  = smem + 2 * TBL_N * 32;
    float*  bufB  = bufA + 128 * BSTR;

    {   // replicate table: entry idx -> 32 lane copies
        float4* st = (float4*)s_tab;
        #pragma unroll 4
        for (int e = threadIdx.x; e < TBL_N * 16; e += 128) {
            float2 cc = __ldg(&g_tab[e >> 4]);
            st[e] = make_float4(cc.x, cc.y, cc.x, cc.y);
        }
    }
    __syncthreads();

    const int tid   = threadIdx.x;
    const int lane  = tid & 31;
    const int wbase = tid & ~31;
    const int la    = lane >> 3;
    const int lb    = lane & 7;
    const int rowblk = blockIdx.x;
    const int c      = blockIdx.y;
    const int row    = rowblk * 128 + tid;

    const unsigned tlane =
        (unsigned)__cvta_generic_to_shared(s_tab) + lane * 8u - 0x40000000u;

    const int t0    = c * LCH - (c ? WARM : 0);
    const int nwarm = c ? (WARM / 32) : 0;       // 5 or 0
    const int N     = nwarm + LCH / 32;          // 21 or 16

    const float* ubase = u + (size_t)(rowblk * 128 + wbase) * T_DIM + t0;
    if (c == 0) out[(size_t)row * (T_DIM + 1)] = 0.0f;

    float K = 0.0f, v = 0.0f;
    float4 R0[8], R1[8];

    auto ldgrow = [&](float4* rg, int g, int r) {
        rg[r] = *(const float4*)(ubase + g * 32 + lb * 4 +
                                 (size_t)(la + 4 * r) * T_DIM);
    };

    auto step = [&](float uu) {
        float up1 = fminf(fmaf(uu, uu, 1.0f), UP_CAP);
        v = fmaf(0.8f, v, 0.2f * uu);
        float w   = fmaf(0.28f, K, 0.52f * v);
        float K08 = 0.8f * K;
        float x   = fminf(fmaf(K, K, up1), X_CAP);
        float y;
        asm("rsqrt.approx.f32 %0, %1;" : "=f"(y) : "f"(x));
        float tf = fmaf(y, CM, CAM);
        float t  = fmaf(y, CM, CA);
        unsigned addr = __float_as_uint(tf) * 256u + tlane;
        float a, b2;
        asm volatile("ld.shared.v2.f32 {%0,%1}, [%2];"
                     : "=f"(a), "=f"(b2) : "r"(addr));
        float g = fmaf(t, a, b2);
        K = fmaf(g, w, K08);
    };

    // Prologue: groups 0,1 into regs; commit group 0 into bufA.
    #pragma unroll
    for (int r = 0; r < 8; ++r) ldgrow(R0, 0, r);
    #pragma unroll
    for (int r = 0; r < 8; ++r) ldgrow(R1, 1, r);
    #pragma unroll
    for (int r = 0; r < 8; ++r)
        *(float4*)(bufA + (wbase + la + 4 * r) * BSTR + lb * 4) = R0[r];
    __syncwarp();

    #pragma unroll 1
    for (int g = 0; g < N; ++g) {
        float*  cur = (g & 1) ? bufB : bufA;     // group g (u -> z in place)
        float*  nxt = (g & 1) ? bufA : bufB;     // g-1 z (flush) / g+1 u (stage)
        float4* Rs  = (g & 1) ? R0 : R1;         // group g+1, stage out
        float4* Rl  = (g & 1) ? R1 : R0;         // fills with group g+2
        const bool fl   = (g >= 1) && (g - 1 >= nwarm);
        const bool dold = (g + 2 < N);
        float* brow = cur + tid * BSTR;
        const int tg = t0 + (g - 1) * 32;        // flush time base
        float* orow = out + (size_t)(rowblk * 128 + wbase) * (T_DIM + 1)
                          + 1 + tg + lane;

        #pragma unroll
        for (int j4 = 0; j4 < 8; ++j4) {
            float4 u4 = *(float4*)(brow + j4 * 4);
            if (fl) {                            // flush quad j4 of group g-1
                #pragma unroll
                for (int q = 0; q < 4; ++q) {
                    int jr = 4 * j4 + q;
                    orow[(size_t)jr * (T_DIM + 1)] =
                        nxt[(wbase + jr) * BSTR + lane];
                }
            }
            if (dold) ldgrow(Rl, g + 2, j4);     // prefetch group g+2
            float4 z4;
            step(u4.x); z4.x = 2.1f * K;
            step(u4.y); z4.y = 2.1f * K;
            step(u4.z); z4.z = 2.1f * K;
            step(u4.w); z4.w = 2.1f * K;
            *(float4*)(brow + j4 * 4) = z4;
            if (j4 >= 1)                         // stage g+1 rows 4(j4-1)..+3
                *(float4*)(nxt + (wbase + la + 4 * (j4 - 1)) * BSTR + lb * 4)
                    = Rs[j4 - 1];
        }
        *(float4*)(nxt + (wbase + la + 28) * BSTR + lb * 4) = Rs[7];
        __syncwarp();
    }

    // Tail: flush group N-1
    {
        float* slast = ((N - 1) & 1) ? bufB : bufA;
        float* orow  = out + (size_t)(rowblk * 128 + wbase) * (T_DIM + 1)
                           + 1 + (t0 + (N - 1) * 32) + lane;
        #pragma unroll 4
        for (int jr = 0; jr < 32; ++jr)
            orow[(size_t)jr * (T_DIM + 1)] = slast[(wbase + jr) * BSTR + lane];
    }
}

// ---------------------------------------------------------------------------
extern "C" void kernel_launch(void* const* d_in, const int* in_sizes, int n_in,
                              void* d_out, int out_size) {
    const float* u = (const float*)d_in[0];
    float* out = (float*)d_out;

    static const int smem_bytes =
        2 * TBL_N * 32 * (int)sizeof(float) + 2 * 128 * BSTR * (int)sizeof(float);
    cudaFuncSetAttribute(scan_kernel, cudaFuncAttributeMaxDynamicSharedMemorySize, smem_bytes);

    qw_kernel<<<1, 128>>>();
    table_val_kernel<<<1, TBL_N>>>();
    table_coef_kernel<<<1, TBL_N>>>();
    scan_kernel<<<dim3(B_DIM / 128, CHUNKS), 128, smem_bytes>>>(u, out);
}

// round 17
// speedup vs baseline: 1.7352x; 1.7352x over previous
#include <cuda_runtime.h>
#include <math.h>

// Poly-based scan: g(k^2+u^2) = deg-19 polynomial in w = (rsqrt(x)-YMID)/YHALF.
// Coefficients computed ON HOST (fp64) each call, passed by value. No setup
// kernels, no __device__ globals, no on-chain memory op.
// Time-chunked 8x512, WARM=192, 256 blocks, 2/SM. R9 staging skeleton.

#define B_DIM 4096
#define T_DIM 4096
#define CHUNKS 8
#define LCH 512
#define WARM 192
#define NDEG 20
#define X_CAP 85.0f
#define UP_CAP 65.0f
#define BSTR 36

struct Coefs { float c[NDEG]; float wm1, wm0; };

__global__ __launch_bounds__(128, 2)
void scan_kernel(const float* __restrict__ u, float* __restrict__ out, Coefs co) {
    extern __shared__ float smem[];
    float* bufA = smem;
    float* bufB = bufA + 128 * BSTR;

    float cf[NDEG];
    #pragma unroll
    for (int i = 0; i < NDEG; ++i) cf[i] = co.c[i];
    const float WM1 = co.wm1, WM0 = co.wm0;

    const int tid = threadIdx.x, lane = tid & 31, wbase = tid & ~31;
    const int la = lane >> 3, lb = lane & 7;
    const int rowblk = blockIdx.x, c = blockIdx.y;
    const int row = rowblk * 128 + tid;

    const int t0 = c * LCH - (c ? WARM : 0);
    const int nwarm = c ? (WARM / 32) : 0;      // 6 or 0 (even)
    const int N = nwarm + LCH / 32;             // 22 or 16 (even)

    const float* ubase = u + (size_t)(rowblk * 128 + wbase) * T_DIM + t0;
    if (c == 0) out[(size_t)row * (T_DIM + 1)] = 0.0f;

    float K = 0.0f, v = 0.0f;
    float4 ua[8], ub[8];

    auto ldg = [&](float4* rg, int g) {
        const float* gp = ubase + g * 32 + lb * 4;
        #pragma unroll
        for (int r = 0; r < 8; ++r)
            rg[r] = *(const float4*)(gp + (size_t)(la + 4 * r) * T_DIM);
    };
    auto sts = [&](float* buf, const float4* rg) {
        #pragma unroll
        for (int r = 0; r < 8; ++r)
            *(float4*)(buf + (wbase + la + 4 * r) * BSTR + lb * 4) = rg[r];
    };
    auto step = [&](float uu) {
        float up1 = fminf(fmaf(uu, uu, 1.0f), UP_CAP);
        v = fmaf(0.8f, v, 0.2f * uu);
        float wk  = fmaf(0.28f, K, 0.52f * v);
        float K08 = 0.8f * K;
        float x   = fminf(fmaf(K, K, up1), X_CAP);
        float y;
        asm("rsqrt.approx.f32 %0, %1;" : "=f"(y) : "f"(x));
        float w = fmaf(y, WM1, WM0);
        float w2 = w * w, w4 = w2 * w2, w8 = w4 * w4, w16 = w8 * w8;
        float p0 = fmaf(cf[1],  w, cf[0]),  p1 = fmaf(cf[3],  w, cf[2]);
        float p2 = fmaf(cf[5],  w, cf[4]),  p3 = fmaf(cf[7],  w, cf[6]);
        float p4 = fmaf(cf[9],  w, cf[8]),  p5 = fmaf(cf[11], w, cf[10]);
        float p6 = fmaf(cf[13], w, cf[12]), p7 = fmaf(cf[15], w, cf[14]);
        float p8 = fmaf(cf[17], w, cf[16]), p9 = fmaf(cf[19], w, cf[18]);
        float q0 = fmaf(p1, w2, p0), q1 = fmaf(p3, w2, p2);
        float q2 = fmaf(p5, w2, p4), q3 = fmaf(p7, w2, p6);
        float q4 = fmaf(p9, w2, p8);
        float r0 = fmaf(q1, w4, q0), r1 = fmaf(q3, w4, q2);
        float g = fmaf(q4, w16, fmaf(r1, w8, r0));
        K = fmaf(g, wk, K08);
    };
    auto compute = [&](float* buf) {
        float* brow = buf + tid * BSTR;
        #pragma unroll
        for (int j4 = 0; j4 < 8; ++j4) {
            float4 u4 = *(float4*)(brow + j4 * 4);
            float4 z4;
            step(u4.x); z4.x = 2.1f * K;
            step(u4.y); z4.y = 2.1f * K;
            step(u4.z); z4.z = 2.1f * K;
            step(u4.w); z4.w = 2.1f * K;
            *(float4*)(brow + j4 * 4) = z4;
        }
    };
    auto flush = [&](const float* buf, int g) {
        int tg = t0 + g * 32;
        #pragma unroll 4
        for (int jr = 0; jr < 32; ++jr) {
            int grow = rowblk * 128 + wbase + jr;
            out[(size_t)grow * (T_DIM + 1) + 1 + tg + lane] =
                buf[(wbase + jr) * BSTR + lane];
        }
    };

    ldg(ua, 0);
    sts(bufA, ua);
    __syncwarp();
    #pragma unroll 1
    for (int g = 0; g < N; g += 2) {
        ldg(ub, g + 1);
        compute(bufA);
        __syncwarp();
        if (g >= nwarm) flush(bufA, g);
        sts(bufB, ub);
        if (g + 2 < N) ldg(ua, g + 2);
        __syncwarp();
        compute(bufB);
        __syncwarp();
        if (g + 1 >= nwarm) flush(bufB, g + 1);
        if (g + 2 < N) sts(bufA, ua);
        __syncwarp();
    }
}

// Host: Chebyshev fit of g(y) = (2/sqrt(2pi)) int_0^5 sech^2(d z) e^{-z^2/2} dz,
// d = sqrt(1/y^2 - 1), on y in [1/sqrt(85), 1]. Deterministic, pure CPU.
static void compute_coefs(Coefs* co) {
    const double PI = 3.14159265358979323846;
    const double Y0 = 1.0 / sqrt(85.0);
    const double YMID = 0.5 * (1.0 + Y0), YHALF = 0.5 * (1.0 - Y0);
    double gn[NDEG];
    for (int j = 0; j < NDEG; ++j) {
        double y = YMID + YHALF * cos(PI * (j + 0.5) / NDEG);
        double s = 1.0 / (y * y) - 1.0;
        if (s < 0.0) s = 0.0;
        double d = sqrt(s);
        const int NQh = 400;
        double h = 5.0 / NQh, acc = 0.0;
        for (int q = 0; q <= NQh; ++q) {
            double z = h * q;
            double w = ((q == 0 || q == NQh) ? 0.5 * h : h) * exp(-0.5 * z * z);
            double t = tanh(d * z);
            acc += w * (1.0 - t * t);
        }
        gn[j] = acc * 2.0 * 0.3989422804014327;
    }
    double C[NDEG];
    for (int k = 0; k < NDEG; ++k) {
        double s = 0.0;
        for (int m = 0; m < NDEG; ++m)
            s += gn[m] * cos(PI * k * (m + 0.5) / NDEG);
        C[k] = s * 2.0 / NDEG;
    }
    C[0] *= 0.5;
    double a[NDEG], t0[NDEG], t1[NDEG], t2[NDEG];
    for (int j = 0; j < NDEG; ++j) { a[j] = 0.0; t0[j] = 0.0; t1[j] = 0.0; t2[j] = 0.0; }
    t0[0] = 1.0; a[0] += C[0];
    t1[1] = 1.0; a[1] += C[1];
    for (int k = 2; k < NDEG; ++k) {
        t2[0] = -t0[0];
        for (int j = 1; j < NDEG; ++j) t2[j] = 2.0 * t1[j - 1] - t0[j];
        for (int j = 0; j < NDEG; ++j) {
            a[j] += C[k] * t2[j];
            t0[j] = t1[j];
            t1[j] = t2[j];
        }
    }
    for (int j = 0; j < NDEG; ++j) co->c[j] = (float)a[j];
    co->wm1 = (float)(1.0 / YHALF);
    co->wm0 = (float)(-YMID / YHALF);
}

extern "C" void kernel_launch(void* const* d_in, const int* in_sizes, int n_in,
                              void* d_out, int out_size) {
    const float* u = (const float*)d_in[0];
    float* out = (float*)d_out;
    Coefs co;
    compute_coefs(&co);
    static const int smem_bytes = 2 * 128 * BSTR * (int)sizeof(float);
    cudaFuncSetAttribute(scan_kernel, cudaFuncAttributeMaxDynamicSharedMemorySize, smem_bytes);
    scan_kernel<<<dim3(B_DIM / 128, CHUNKS), 128, smem_bytes>>>(u, out, co);
}